// round 16
// baseline (speedup 1.0000x reference)
#include <cuda_runtime.h>
#include <cuda_fp16.h>
#include <math.h>

#define NN 10000
#define NE 200000
#define D  256
#define EPSF 1e-6f

typedef unsigned long long u64;

// ---------------- scratch (device globals: no allocation allowed) ----------
__device__ __align__(128) float g_u[NN * D];
__device__ __align__(128) float g_h[NN * D];
__device__ __align__(128) float g_xp[NN * D];
__device__ __align__(128) __half g_xph[NN * D];    // fp16 xp
__device__ __align__(128) __half g_xtanh[NN * D];  // fp16 xtan
__device__ __align__(128) __half g_Qh[NN * D];
__device__ __align__(128) __half g_P1h[NN * D];
__device__ __align__(128) __half g_P2h[NN * D];
__device__ __align__(128) float g_H[NN * D];
__device__ __align__(128) float g_agg[NN * D];
__device__ __align__(128) float g_S[NN];
// fragment-packed weight images
__device__ __align__(128) unsigned g_WlinP[65536];      // tf32 packed
__device__ __align__(128) unsigned g_We2P[65536];       // tf32 packed
__device__ __align__(128) unsigned g_WqpP[3 * 32768];   // fp16 packed

// ---------------- tf32 helpers ------------------------------------------------
__device__ __forceinline__ unsigned t32(float f) {
    unsigned r; asm("cvt.rna.tf32.f32 %0,%1;" : "=r"(r) : "f"(f)); return r;
}
__device__ __forceinline__ void mma_tf32(float* d, const uint4& a, const uint2& b) {
    asm volatile(
        "mma.sync.aligned.m16n8k8.row.col.f32.tf32.tf32.f32 "
        "{%0,%1,%2,%3},{%4,%5,%6,%7},{%8,%9},{%0,%1,%2,%3};"
        : "+f"(d[0]), "+f"(d[1]), "+f"(d[2]), "+f"(d[3])
        : "r"(a.x), "r"(a.y), "r"(a.z), "r"(a.w), "r"(b.x), "r"(b.y));
}
__device__ __forceinline__ void mma_f16(float* d, const uint4& a, const uint2& b) {
    asm volatile(
        "mma.sync.aligned.m16n8k16.row.col.f32.f16.f16.f32 "
        "{%0,%1,%2,%3},{%4,%5,%6,%7},{%8,%9},{%0,%1,%2,%3};"
        : "+f"(d[0]), "+f"(d[1]), "+f"(d[2]), "+f"(d[3])
        : "r"(a.x), "r"(a.y), "r"(a.z), "r"(a.w), "r"(b.x), "r"(b.y));
}

// ---------------- misc helpers ------------------------------------------------
__device__ __forceinline__ float warpSum(float v) {
    #pragma unroll
    for (int o = 16; o > 0; o >>= 1) v += __shfl_xor_sync(0xffffffffu, v, o);
    return v;
}
__device__ __forceinline__ float siluf(float x) { return x / (1.f + expf(-x)); }
__device__ __forceinline__ float tanh_ap(float x) {
    float y; asm("tanh.approx.f32 %0,%1;" : "=f"(y) : "f"(x)); return y;
}
__device__ __forceinline__ float sigm_fast(float x) {
    return fmaf(0.5f, tanh_ap(0.5f * x), 0.5f);
}
__device__ __forceinline__ float silu_fast(float x) { return x * sigm_fast(x); }

__device__ __forceinline__ void ld8h(const __half* p, float* o) {
    uint4 v = *(const uint4*)p;
    __half2 h0 = *(__half2*)&v.x, h1 = *(__half2*)&v.y,
            h2 = *(__half2*)&v.z, h3 = *(__half2*)&v.w;
    float2 f;
    f = __half22float2(h0); o[0] = f.x; o[1] = f.y;
    f = __half22float2(h1); o[2] = f.x; o[3] = f.y;
    f = __half22float2(h2); o[4] = f.x; o[5] = f.y;
    f = __half22float2(h3); o[6] = f.x; o[7] = f.y;
}

// ---------------- tf32 staging helpers (shared by GEMM + pack) ---------------
struct StA { float4 f00, f01, f10, f11; };
struct StB { float2 g[8]; };

__device__ __forceinline__ void mma_stage_fetchA(StA& st, const float* pa0,
                                                 const float* pa1, bool ok0,
                                                 bool ok1) {
    const float4 z4 = make_float4(0.f, 0.f, 0.f, 0.f);
    st.f00 = ok0 ? *(const float4*)(pa0)     : z4;
    st.f01 = ok0 ? *(const float4*)(pa0 + 4) : z4;
    st.f10 = ok1 ? *(const float4*)(pa1)     : z4;
    st.f11 = ok1 ? *(const float4*)(pa1 + 4) : z4;
}
__device__ __forceinline__ void mma_stage_storeA(unsigned* dst, const StA& st) {
    const float* a00 = &st.f00.x;
    const float* a01 = &st.f01.x;
    const float* a10 = &st.f10.x;
    const float* a11 = &st.f11.x;
    #pragma unroll
    for (int dl = 0; dl < 4; dl++) {
        uint4 v = make_uint4(t32(a00[dl]), t32(a10[dl]), t32(a01[dl]), t32(a11[dl]));
        ((uint4*)dst)[dl] = v;
    }
}
__device__ __forceinline__ void mma_stage_fetchB(StB& st, const float* pb) {
    #pragma unroll
    for (int j = 0; j < 8; j++) st.g[j] = *(const float2*)(pb + j * 256);
}
__device__ __forceinline__ void mma_stage_storeB(unsigned* dst, const StB& st) {
    uint4 v0 = make_uint4(t32(st.g[0].x), t32(st.g[4].x), t32(st.g[1].x), t32(st.g[5].x));
    uint4 v1 = make_uint4(t32(st.g[2].x), t32(st.g[6].x), t32(st.g[3].x), t32(st.g[7].x));
    uint4 v2 = make_uint4(t32(st.g[0].y), t32(st.g[4].y), t32(st.g[1].y), t32(st.g[5].y));
    uint4 v3 = make_uint4(t32(st.g[2].y), t32(st.g[6].y), t32(st.g[3].y), t32(st.g[7].y));
    ((uint4*)dst)[0] = v0; ((uint4*)dst)[1] = v1;
    ((uint4*)dst)[2] = v2; ((uint4*)dst)[3] = v3;
}

// ---------------- fused: logmap0 + zero + weight fragment-packing ------------
#define LOG_BLOCKS (NN / 8)
__global__ __launch_bounds__(256) void k_logmap0_fused(
    const float* __restrict__ x, const float* __restrict__ We1,
    const float* __restrict__ Wa1, const float* __restrict__ Wlin,
    const float* __restrict__ We2) {
    int b = blockIdx.x;
    int tid = threadIdx.x;
    if (b >= LOG_BLOCKS) {
        int pb = b - LOG_BLOCKS;
        if (pb < 32) {
            const float* W = (pb < 16) ? Wlin : We2;
            unsigned* P = (pb < 16) ? g_WlinP : g_We2P;
            int t = (pb & 15) * 256 + tid;
            int half = t & 1;
            int tt = (t >> 1) & 127;
            int kb = (t >> 8) & 7;
            int colBlk = t >> 11;
            const float* pbs = W + ((tt >> 2) & 3) * 8 * 256 + colBlk * 128 +
                               (tt >> 4) * 8 + 2 * (tt & 3) + half * 64 +
                               kb * 32 * 256;
            StB st; mma_stage_fetchB(st, pbs);
            mma_stage_storeB(P + colBlk * 32768 + kb * 4096 + half * 2048 + tt * 16, st);
        } else {
            int t = (pb - 32) * 256 + tid;
            int m = t >> 11;
            int tt = t & 2047;
            int tid128 = tt & 127;
            int kb = (tt >> 7) & 7;
            int colBlk = tt >> 10;
            const float* W = (m == 0) ? We1 : Wa1 + (m - 1) * 256 * 256;
            unsigned* P = g_WqpP + m * 32768 + colBlk * 16384 + kb * 2048;
            int kp2 = tid128 & 15;
            int nblk = tid128 >> 4;
            int bs = kp2 >> 3;
            int kk = kp2 & 7;
            int bl4 = kk & 3;
            int breg = kk >> 2;
            int k0 = kb * 32 + kp2 * 2;
            #pragma unroll
            for (int wi = 0; wi < 8; wi++) {
                int n0 = nblk * 16 + wi * 2;
                int cabs = colBlk * 128 + n0;
                __half2 f0 = __floats2half2_rn(W[(size_t)k0 * 256 + cabs],
                                               W[(size_t)(k0 + 1) * 256 + cabs]);
                __half2 f1 = __floats2half2_rn(W[(size_t)k0 * 256 + cabs + 1],
                                               W[(size_t)(k0 + 1) * 256 + cabs + 1]);
                int gn = n0 >> 3;
                int l0 = n0 & 7;
                P[((gn * 2 + bs) * 32 + l0 * 4 + bl4) * 2 + breg] = *(unsigned*)&f0;
                P[((gn * 2 + bs) * 32 + (l0 + 1) * 4 + bl4) * 2 + breg] = *(unsigned*)&f1;
            }
        }
        return;
    }
    int node = b * 8 + (tid >> 5);
    int lane = tid & 31;
    int base = lane * 8;

    float xv[8];
    const float* xp = x + (size_t)node * D + base;
    *(float4*)&xv[0] = *(const float4*)(xp);
    *(float4*)&xv[4] = *(const float4*)(xp + 4);

    float x0 = fmaxf(__shfl_sync(0xffffffffu, xv[0], 0), 1.f + EPSF);
    float sc = acoshf(x0) / sqrtf(x0 * x0 - 1.f);

    float uo[8];
    #pragma unroll
    for (int i = 0; i < 8; i++) uo[i] = sc * xv[i];
    if (lane == 0) uo[0] = 0.f;

    float* up = g_u + (size_t)node * D + base;
    *(float4*)(up)     = *(float4*)&uo[0];
    *(float4*)(up + 4) = *(float4*)&uo[4];

    const float4 z4 = make_float4(0.f, 0.f, 0.f, 0.f);
    float* Hp = g_H + (size_t)node * D + base;
    *(float4*)(Hp)     = z4;
    *(float4*)(Hp + 4) = z4;
    if (lane == 0) g_S[node] = 0.f;
}

// ---------------- tf32 MMA GEMM: 256 thr, 8 warps (4x2), BM=64 BN=128 --------
// Warps 0-3 stage A (layout identical to 128-thread version); warps 4-7 copy
// pre-packed B. Warp tile 16x64.
__device__ __forceinline__ void mma_gemm_body_f32(const float* __restrict__ A,
                                                  const unsigned* __restrict__ PB,
                                                  float* __restrict__ C, int M) {
    __shared__ __align__(16) unsigned smA[2][2048];
    __shared__ __align__(16) unsigned smB[2][4096];
    int tid = threadIdx.x;
    int lane = tid & 31;
    int w = tid >> 5;
    int wm = w & 3, wn = w >> 2;
    int rowBase = blockIdx.y * 64;
    bool isA = tid < 128;
    int t128 = tid & 127;

    int aRow0 = rowBase + (t128 >> 5) * 16 + (t128 & 7);
    const float* pa0 = A + (size_t)aRow0 * 256 + ((t128 >> 3) & 3) * 8;
    const float* pa1 = pa0 + 8 * 256;
    bool ok0 = (aRow0 < M) && isA, ok1 = (aRow0 + 8 < M) && isA;
    const uint4* pbp = (const uint4*)(PB + blockIdx.x * 32768);

    StA stA;
    uint4 rb[8];
    if (isA) {
        mma_stage_fetchA(stA, pa0, pa1, ok0, ok1);
        mma_stage_storeA(&smA[0][t128 * 16], stA);
    } else {
        #pragma unroll
        for (int q = 0; q < 8; q++) rb[q] = pbp[q * 128 + t128];
        #pragma unroll
        for (int q = 0; q < 8; q++) ((uint4*)smB[0])[q * 128 + t128] = rb[q];
    }
    __syncthreads();

    float d[8][4];
    #pragma unroll
    for (int u = 0; u < 8; u++)
        #pragma unroll
        for (int c = 0; c < 4; c++) d[u][c] = 0.f;

    int buf = 0;
    for (int kb = 0; kb < 8; kb++) {
        if (kb < 7) {
            if (isA)
                mma_stage_fetchA(stA, pa0 + (kb + 1) * 32, pa1 + (kb + 1) * 32, ok0, ok1);
            else {
                #pragma unroll
                for (int q = 0; q < 8; q++)
                    rb[q] = pbp[(kb + 1) * 1024 + q * 128 + t128];
            }
        }
        #pragma unroll
        for (int s = 0; s < 4; s++) {
            uint4 fa = *(const uint4*)&smA[buf][(wm * 4 + s) * 128 + lane * 4];
            uint2 fb[8];
            #pragma unroll
            for (int u = 0; u < 8; u++)
                fb[u] = *(const uint2*)&smB[buf][wn * 2048 + (u * 4 + s) * 64 + lane * 2];
            #pragma unroll
            for (int u = 0; u < 8; u++) mma_tf32(d[u], fa, fb[u]);
        }
        if (kb < 7) {
            int nb = buf ^ 1;
            if (isA)
                mma_stage_storeA(&smA[nb][t128 * 16], stA);
            else {
                #pragma unroll
                for (int q = 0; q < 8; q++) ((uint4*)smB[nb])[q * 128 + t128] = rb[q];
            }
            __syncthreads();
            buf = nb;
        }
    }

    int colBase = blockIdx.x * 128;
    int r0 = rowBase + wm * 16 + (lane >> 2);
    int r1 = r0 + 8;
    #pragma unroll
    for (int u = 0; u < 8; u++) {
        int c0 = colBase + wn * 64 + u * 8 + (lane & 3) * 2;
        if (r0 < M)
            *(float2*)(C + (size_t)r0 * 256 + c0) = make_float2(d[u][0], d[u][1]);
        if (r1 < M)
            *(float2*)(C + (size_t)r1 * 256 + c0) = make_float2(d[u][2], d[u][3]);
    }
}

__global__ __launch_bounds__(256, 2) void mma_lin() {
    mma_gemm_body_f32(g_u, g_WlinP, g_h, NN);
}
__global__ __launch_bounds__(256, 2) void mma_agg() {
    mma_gemm_body_f32(g_H, g_We2P, g_agg, NN);
}

// ---------------- fp16 MMA GEMM (m16n8k16): 256 thr, 8 warps (4x2) -----------
__global__ __launch_bounds__(256, 2) void mma_qph() {
    int z = blockIdx.z;
    const __half* A = (z == 0) ? g_xph : g_xtanh;
    __half* C = (z == 0) ? g_Qh : (z == 1 ? g_P1h : g_P2h);
    const int M = NN;

    __shared__ __align__(16) unsigned smA[2][1024];
    __shared__ __align__(16) unsigned smB[2][2048];
    int tid = threadIdx.x;
    int lane = tid & 31;
    int w = tid >> 5;
    int wm = w & 3, wn = w >> 2;
    int rowBase = blockIdx.y * 64;
    int colBase = blockIdx.x * 128;
    bool isA = tid < 128;
    int t128 = tid & 127;

    int ar = t128 >> 1;
    int as = t128 & 1;
    int aRow = rowBase + ar;
    bool aok = (aRow < M) && isA;
    const __half* pa = A + (size_t)aRow * 256 + as * 16;
    int ag = ar >> 4;
    int rr = ar & 15;
    int abase = ((ag * 2 + as) * 32 + (rr & 7) * 4) * 4 + (rr >> 3);
    const uint4* pbp = (const uint4*)(g_WqpP + z * 32768 + blockIdx.x * 16384);

    const uint4 zz = make_uint4(0u, 0u, 0u, 0u);
    uint4 va, vb, rb[4];

    if (isA) {
        va = aok ? *(const uint4*)(pa)     : zz;
        vb = aok ? *(const uint4*)(pa + 8) : zz;
        unsigned* dA = &smA[0][abase];
        dA[0] = va.x; dA[4] = va.y; dA[8]  = va.z; dA[12] = va.w;
        dA[2] = vb.x; dA[6] = vb.y; dA[10] = vb.z; dA[14] = vb.w;
    } else {
        #pragma unroll
        for (int q = 0; q < 4; q++) rb[q] = pbp[q * 128 + t128];
        #pragma unroll
        for (int q = 0; q < 4; q++) ((uint4*)smB[0])[q * 128 + t128] = rb[q];
    }
    __syncthreads();

    float d[8][4];
    #pragma unroll
    for (int u = 0; u < 8; u++)
        #pragma unroll
        for (int c = 0; c < 4; c++) d[u][c] = 0.f;

    int buf = 0;
    for (int kb = 0; kb < 8; kb++) {
        if (kb < 7) {
            if (isA) {
                const __half* pan = pa + (kb + 1) * 32;
                va = aok ? *(const uint4*)(pan)     : zz;
                vb = aok ? *(const uint4*)(pan + 8) : zz;
            } else {
                #pragma unroll
                for (int q = 0; q < 4; q++)
                    rb[q] = pbp[(kb + 1) * 512 + q * 128 + t128];
            }
        }
        #pragma unroll
        for (int s = 0; s < 2; s++) {
            uint4 fa = *(const uint4*)&smA[buf][((wm * 2 + s) * 32 + lane) * 4];
            uint2 fb[8];
            #pragma unroll
            for (int u = 0; u < 8; u++)
                fb[u] = *(const uint2*)&smB[buf][(((wn * 8 + u) * 2 + s) * 32 + lane) * 2];
            #pragma unroll
            for (int u = 0; u < 8; u++) mma_f16(d[u], fa, fb[u]);
        }
        if (kb < 7) {
            int nb = buf ^ 1;
            if (isA) {
                unsigned* dA = &smA[nb][abase];
                dA[0] = va.x; dA[4] = va.y; dA[8]  = va.z; dA[12] = va.w;
                dA[2] = vb.x; dA[6] = vb.y; dA[10] = vb.z; dA[14] = vb.w;
            } else {
                #pragma unroll
                for (int q = 0; q < 4; q++) ((uint4*)smB[nb])[q * 128 + t128] = rb[q];
            }
            __syncthreads();
            buf = nb;
        }
    }

    int r0 = rowBase + wm * 16 + (lane >> 2);
    int r1 = r0 + 8;
    #pragma unroll
    for (int u = 0; u < 8; u++) {
        int c0 = colBase + wn * 64 + u * 8 + (lane & 3) * 2;
        if (r0 < M)
            *(__half2*)(C + (size_t)r0 * 256 + c0) =
                __floats2half2_rn(d[u][0], d[u][1]);
        if (r1 < M)
            *(__half2*)(C + (size_t)r1 * 256 + c0) =
                __floats2half2_rn(d[u][2], d[u][3]);
    }
}

// ---------------- node prep: one warp per node --------------------------------
__global__ __launch_bounds__(256) void k_node_xp(const float* __restrict__ bias) {
    int node = blockIdx.x * 8 + (threadIdx.x >> 5);
    int lane = threadIdx.x & 31;
    int base = lane * 8;

    float h[8];
    const float* hp = g_h + (size_t)node * D + base;
    *(float4*)&h[0] = *(const float4*)(hp);
    *(float4*)&h[4] = *(const float4*)(hp + 4);
    if (lane == 0) h[0] = 0.f;

    float acc = 0.f;
    #pragma unroll
    for (int i = 0; i < 8; i++) acc += h[i] * h[i];
    float r1 = warpSum(acc);
    float nn = sqrtf(fmaxf(r1, EPSF));
    float sh_n = sinhf(nn) / nn;
    float xp00 = coshf(nn);
    float xp0[8];
    #pragma unroll
    for (int i = 0; i < 8; i++) xp0[i] = sh_n * h[i];
    if (lane == 0) xp0[0] = xp00;

    float b[8];
    *(float4*)&b[0] = *(const float4*)(bias + base);
    *(float4*)&b[4] = *(const float4*)(bias + base + 4);
    if (lane == 0) b[0] = 0.f;

    acc = 0.f;
    #pragma unroll
    for (int i = 0; i < 8; i++) acc += xp0[i] * b[i];
    float c = warpSum(acc);
    float fac = c / (1.f + xp00);
    float u[8];
    #pragma unroll
    for (int i = 0; i < 8; i++) u[i] = b[i] + fac * xp0[i];
    if (lane == 0) u[0] += fac;

    acc = 0.f;
    #pragma unroll
    for (int i = 0; i < 8; i++) acc += u[i] * u[i];
    float su2 = warpSum(acc);
    float lin = su2 - 2.f * c * c;
    float nu = sqrtf(fmaxf(lin, EPSF));
    float ch = coshf(nu), sh = sinhf(nu) / nu;

    float xp[8];
    #pragma unroll
    for (int i = 0; i < 8; i++) xp[i] = ch * xp0[i] + sh * u[i];
    float* xpp = g_xp + (size_t)node * D + base;
    *(float4*)(xpp)     = *(float4*)&xp[0];
    *(float4*)(xpp + 4) = *(float4*)&xp[4];

    {
        __half2 q0 = __floats2half2_rn(xp[0], xp[1]);
        __half2 q1 = __floats2half2_rn(xp[2], xp[3]);
        __half2 q2 = __floats2half2_rn(xp[4], xp[5]);
        __half2 q3 = __floats2half2_rn(xp[6], xp[7]);
        uint4 o;
        o.x = *(unsigned*)&q0; o.y = *(unsigned*)&q1;
        o.z = *(unsigned*)&q2; o.w = *(unsigned*)&q3;
        *(uint4*)(g_xph + (size_t)node * D + base) = o;
    }

    float xpc0 = ch * xp00 + sh * c;
    float x0c = fmaxf(xpc0, 1.f + EPSF);
    float sc = acoshf(x0c) / sqrtf(x0c * x0c - 1.f);
    float xt[8];
    #pragma unroll
    for (int i = 0; i < 8; i++) xt[i] = sc * xp[i];
    if (lane == 0) xt[0] = 0.f;
    {
        __half2 q0 = __floats2half2_rn(xt[0], xt[1]);
        __half2 q1 = __floats2half2_rn(xt[2], xt[3]);
        __half2 q2 = __floats2half2_rn(xt[4], xt[5]);
        __half2 q3 = __floats2half2_rn(xt[6], xt[7]);
        uint4 o;
        o.x = *(unsigned*)&q0; o.y = *(unsigned*)&q1;
        o.z = *(unsigned*)&q2; o.w = *(unsigned*)&q3;
        *(uint4*)(g_xtanh + (size_t)node * D + base) = o;
    }
}

// ---------------- edge kernel: 32 edges per block (4 per warp), fp16 gathers --
__global__ __launch_bounds__(256) void k_edge(
    const float* __restrict__ eattr, const int* __restrict__ row,
    const int* __restrict__ col, const float* __restrict__ emask,
    const float* __restrict__ Wa1, const float* __restrict__ ba1,
    const float* __restrict__ Wa2, const float* __restrict__ ba2,
    const float* __restrict__ We1, const float* __restrict__ be1) {
    __shared__ float sw[8][256];
    int tid = threadIdx.x;
    sw[0][tid] = Wa1[512 * D + tid];
    sw[1][tid] = Wa1[513 * D + tid];
    sw[2][tid] = ba1[tid];
    sw[3][tid] = Wa2[tid];
    sw[4][tid] = We1[tid];
    sw[5][tid] = We1[256 * D + tid];
    sw[6][tid] = We1[257 * D + tid];
    sw[7][tid] = be1[tid];
    __syncthreads();

    int warp = tid >> 5;
    int lane = tid & 31;
    int base = lane * 8;
    float ba2v = ba2[0];

    #pragma unroll
    for (int it = 0; it < 4; it++) {
        int e = blockIdx.x * 32 + it * 8 + warp;

        int r = row[e];
        int c = col[e];

        float xr[8], xc[8];
        ld8h(g_xph + (size_t)r * D + base, xr);
        ld8h(g_xph + (size_t)c * D + base, xc);

        float part = 0.f;
        #pragma unroll
        for (int i = 0; i < 8; i++) part -= xr[i] * xc[i];
        part = warpSum(part);

        float x0 = __shfl_sync(0xffffffffu, xr[0], 0);
        float y0 = __shfl_sync(0xffffffffu, xc[0], 0);

        float a = fmaxf(part + 2.f * x0 * y0, 1.f + EPSF);
        float dd = acoshf(a);
        float q = sqrtf(a * a - 1.f);
        float s = dd / q;
        float v0 = s * (y0 - a * x0);
        float beta = -v0 / (1.f + x0);
        float alpha = beta - s * a;

        float ea0 = eattr[e];
        float m = emask[e];

        float P1v[8], P2v[8];
        ld8h(g_P1h + (size_t)r * D + base, P1v);
        ld8h(g_P2h + (size_t)c * D + base, P2v);

        float lp = 0.f;
        #pragma unroll
        for (int i = 0; i < 8; i++) {
            int j = base + i;
            float ha = P1v[i] + P2v[i] + ea0 * sw[0][j] + dd * sw[1][j] + sw[2][j];
            lp += silu_fast(ha) * sw[3][j];
        }
        lp = warpSum(lp);
        float att = m * sigm_fast(lp + ba2v);

        float QR[8], QC[8];
        ld8h(g_Qh + (size_t)r * D + base, QR);
        ld8h(g_Qh + (size_t)c * D + base, QC);

        float val[8];
        #pragma unroll
        for (int i = 0; i < 8; i++) {
            int j = base + i;
            float hm = alpha * QR[i] + s * QC[i] + beta * sw[4][j] +
                       ea0 * sw[5][j] + dd * sw[6][j] + sw[7][j];
            val[i] = att * silu_fast(hm);
        }

        float* Hr = g_H + (size_t)r * D + base;
        asm volatile("red.global.add.v4.f32 [%0], {%1,%2,%3,%4};"
                     :: "l"(Hr), "f"(val[0]), "f"(val[1]), "f"(val[2]), "f"(val[3])
                     : "memory");
        asm volatile("red.global.add.v4.f32 [%0], {%1,%2,%3,%4};"
                     :: "l"(Hr + 4), "f"(val[4]), "f"(val[5]), "f"(val[6]), "f"(val[7])
                     : "memory");
        if (lane == 0) atomicAdd(&g_S[r], att);
    }
}

// ---------------- final node kernel: one warp per node -----------------------
__global__ __launch_bounds__(256) void k_final(const float* __restrict__ be2,
                                               const float* __restrict__ lng,
                                               const float* __restrict__ lnb,
                                               float* __restrict__ out) {
    int node = blockIdx.x * 8 + (threadIdx.x >> 5);
    int lane = threadIdx.x & 31;
    int base = lane * 8;

    float Sv = g_S[node];
    float ag[8], be[8], xp[8];
    const float* agp = g_agg + (size_t)node * D + base;
    *(float4*)&ag[0] = *(const float4*)(agp);
    *(float4*)&ag[4] = *(const float4*)(agp + 4);
    *(float4*)&be[0] = *(const float4*)(be2 + base);
    *(float4*)&be[4] = *(const float4*)(be2 + base + 4);
    const float* xpp = g_xp + (size_t)node * D + base;
    *(float4*)&xp[0] = *(const float4*)(xpp);
    *(float4*)&xp[4] = *(const float4*)(xpp + 4);

    #pragma unroll
    for (int i = 0; i < 8; i++) ag[i] += Sv * be[i];
    if (lane == 0) ag[0] = 0.f;

    float xp0 = __shfl_sync(0xffffffffu, xp[0], 0);

    float acc = 0.f;
    #pragma unroll
    for (int i = 0; i < 8; i++) acc += xp[i] * ag[i];
    float cc = warpSum(acc);
    float fac = cc / (1.f + xp0);
    float sup[8];
    #pragma unroll
    for (int i = 0; i < 8; i++) sup[i] = ag[i] + fac * xp[i];
    if (lane == 0) sup[0] += fac;

    acc = 0.f;
    #pragma unroll
    for (int i = 0; i < 8; i++) acc += sup[i] * sup[i];
    float su2 = warpSum(acc);
    float lin = su2 - 2.f * cc * cc;
    float nu = sqrtf(fmaxf(lin, EPSF));
    float ch = coshf(nu), sh = sinhf(nu) / nu;

    float y[8];
    #pragma unroll
    for (int i = 0; i < 8; i++) y[i] = ch * xp[i] + sh * sup[i];
    float y0 = ch * xp0 + sh * cc;

    float y0c = fmaxf(y0, 1.f + EPSF);
    float sc = acoshf(y0c) / sqrtf(y0c * y0c - 1.f);
    float xo[8];
    #pragma unroll
    for (int i = 0; i < 8; i++) xo[i] = sc * y[i];
    if (lane == 0) xo[0] = 0.f;

    acc = 0.f;
    #pragma unroll
    for (int i = 0; i < 8; i++) acc += xo[i];
    float mean = warpSum(acc) * (1.f / 255.f);
    float dev[8];
    #pragma unroll
    for (int i = 0; i < 8; i++) dev[i] = xo[i] - mean;
    if (lane == 0) dev[0] = 0.f;
    acc = 0.f;
    #pragma unroll
    for (int i = 0; i < 8; i++) acc += dev[i] * dev[i];
    float var = warpSum(acc) * (1.f / 255.f);
    float inv = 1.f / sqrtf(var + 1e-5f);

    float sl[8];
    #pragma unroll
    for (int i = 0; i < 8; i++) {
        int j = base + i;
        float lg = (j > 0) ? lng[j - 1] : 0.f;
        float lb = (j > 0) ? lnb[j - 1] : 0.f;
        float ln = dev[i] * inv * lg + lb;
        sl[i] = siluf(ln);
    }
    if (lane == 0) sl[0] = 0.f;

    acc = 0.f;
    #pragma unroll
    for (int i = 0; i < 8; i++) acc += sl[i] * sl[i];
    float n2 = warpSum(acc);
    float nn = sqrtf(fmaxf(n2, EPSF));
    float shn = sinhf(nn) / nn;

    float o[8];
    #pragma unroll
    for (int i = 0; i < 8; i++) o[i] = shn * sl[i];
    if (lane == 0) o[0] = coshf(nn);
    float* op = out + (size_t)node * D + base;
    *(float4*)(op)     = *(float4*)&o[0];
    *(float4*)(op + 4) = *(float4*)&o[4];
}

// ---------------- launch -----------------------------------------------------
extern "C" void kernel_launch(void* const* d_in, const int* in_sizes, int n_in,
                              void* d_out, int out_size) {
    const float* x     = (const float*)d_in[0];
    const float* eattr = (const float*)d_in[1];
    const int*   row   = (const int*)d_in[2];
    const int*   col   = (const int*)d_in[3];
    const float* emask = (const float*)d_in[5];
    const float* W_lin = (const float*)d_in[6];
    const float* bias  = (const float*)d_in[7];
    const float* W_e1  = (const float*)d_in[8];
    const float* b_e1  = (const float*)d_in[9];
    const float* W_e2  = (const float*)d_in[10];
    const float* b_e2  = (const float*)d_in[11];
    const float* W_a1  = (const float*)d_in[12];
    const float* b_a1  = (const float*)d_in[13];
    const float* W_a2  = (const float*)d_in[14];
    const float* b_a2  = (const float*)d_in[15];
    const float* ln_g  = (const float*)d_in[16];
    const float* ln_b  = (const float*)d_in[17];
    float* out = (float*)d_out;

    dim3 gMma(2, (NN + 63) / 64);
    dim3 gMmaQP(2, (NN + 63) / 64, 3);

    k_logmap0_fused<<<LOG_BLOCKS + 56, 256>>>(x, W_e1, W_a1, W_lin, W_e2);
    mma_lin<<<gMma, 256>>>();                           // tf32, packed B, 8 warps
    k_node_xp<<<NN / 8, 256>>>(bias);
    mma_qph<<<gMmaQP, 256>>>();                         // fp16, packed B, 8 warps
    k_edge<<<NE / 32, 256>>>(eattr, row, col, emask, W_a1, b_a1, W_a2, b_a2, W_e1, b_e1);
    mma_agg<<<gMma, 256>>>();                           // tf32, packed B, 8 warps
    k_final<<<NN / 8, 256>>>(b_e2, ln_g, ln_b, out);
}

// round 17
// speedup vs baseline: 1.0213x; 1.0213x over previous
#include <cuda_runtime.h>
#include <cuda_fp16.h>
#include <math.h>

#define NN 10000
#define NE 200000
#define D  256
#define EPSF 1e-6f

typedef unsigned long long u64;

// ---------------- scratch (device globals: no allocation allowed) ----------
__device__ __align__(128) float g_u[NN * D];
__device__ __align__(128) float g_h[NN * D];
__device__ __align__(128) float g_xp[NN * D];
__device__ __align__(128) __half g_xph[NN * D];    // fp16 xp
__device__ __align__(128) __half g_xtanh[NN * D];  // fp16 xtan
__device__ __align__(128) __half g_Qh[NN * D];
__device__ __align__(128) __half g_P1h[NN * D];
__device__ __align__(128) __half g_P2h[NN * D];
__device__ __align__(128) float g_H[NN * D];
__device__ __align__(128) float g_agg[NN * D];
__device__ __align__(128) float g_S[NN];
// fragment-packed weight images
__device__ __align__(128) unsigned g_WlinP[65536];      // tf32 packed
__device__ __align__(128) unsigned g_We2P[65536];       // tf32 packed
__device__ __align__(128) unsigned g_WqpP[3 * 32768];   // fp16 packed

// ---------------- tf32 helpers ------------------------------------------------
__device__ __forceinline__ unsigned t32(float f) {
    unsigned r; asm("cvt.rna.tf32.f32 %0,%1;" : "=r"(r) : "f"(f)); return r;
}
__device__ __forceinline__ void mma_tf32(float* d, const uint4& a, const uint2& b) {
    asm volatile(
        "mma.sync.aligned.m16n8k8.row.col.f32.tf32.tf32.f32 "
        "{%0,%1,%2,%3},{%4,%5,%6,%7},{%8,%9},{%0,%1,%2,%3};"
        : "+f"(d[0]), "+f"(d[1]), "+f"(d[2]), "+f"(d[3])
        : "r"(a.x), "r"(a.y), "r"(a.z), "r"(a.w), "r"(b.x), "r"(b.y));
}
__device__ __forceinline__ void mma_f16(float* d, const uint4& a, const uint2& b) {
    asm volatile(
        "mma.sync.aligned.m16n8k16.row.col.f32.f16.f16.f32 "
        "{%0,%1,%2,%3},{%4,%5,%6,%7},{%8,%9},{%0,%1,%2,%3};"
        : "+f"(d[0]), "+f"(d[1]), "+f"(d[2]), "+f"(d[3])
        : "r"(a.x), "r"(a.y), "r"(a.z), "r"(a.w), "r"(b.x), "r"(b.y));
}

// ---------------- misc helpers ------------------------------------------------
__device__ __forceinline__ float warpSum(float v) {
    #pragma unroll
    for (int o = 16; o > 0; o >>= 1) v += __shfl_xor_sync(0xffffffffu, v, o);
    return v;
}
__device__ __forceinline__ float siluf(float x) { return x / (1.f + expf(-x)); }
__device__ __forceinline__ float tanh_ap(float x) {
    float y; asm("tanh.approx.f32 %0,%1;" : "=f"(y) : "f"(x)); return y;
}
__device__ __forceinline__ float sigm_fast(float x) {
    return fmaf(0.5f, tanh_ap(0.5f * x), 0.5f);
}
__device__ __forceinline__ float silu_fast(float x) { return x * sigm_fast(x); }

__device__ __forceinline__ void ld8h(const __half* p, float* o) {
    uint4 v = *(const uint4*)p;
    __half2 h0 = *(__half2*)&v.x, h1 = *(__half2*)&v.y,
            h2 = *(__half2*)&v.z, h3 = *(__half2*)&v.w;
    float2 f;
    f = __half22float2(h0); o[0] = f.x; o[1] = f.y;
    f = __half22float2(h1); o[2] = f.x; o[3] = f.y;
    f = __half22float2(h2); o[4] = f.x; o[5] = f.y;
    f = __half22float2(h3); o[6] = f.x; o[7] = f.y;
}

// ---------------- tf32 staging helpers (shared by GEMM + pack) ---------------
struct StA { float4 f00, f01, f10, f11; };
struct StB { float2 g[8]; };

__device__ __forceinline__ void mma_stage_fetchA(StA& st, const float* pa0,
                                                 const float* pa1, bool ok0,
                                                 bool ok1) {
    const float4 z4 = make_float4(0.f, 0.f, 0.f, 0.f);
    st.f00 = ok0 ? *(const float4*)(pa0)     : z4;
    st.f01 = ok0 ? *(const float4*)(pa0 + 4) : z4;
    st.f10 = ok1 ? *(const float4*)(pa1)     : z4;
    st.f11 = ok1 ? *(const float4*)(pa1 + 4) : z4;
}
__device__ __forceinline__ void mma_stage_storeA(unsigned* dst, const StA& st) {
    const float* a00 = &st.f00.x;
    const float* a01 = &st.f01.x;
    const float* a10 = &st.f10.x;
    const float* a11 = &st.f11.x;
    #pragma unroll
    for (int dl = 0; dl < 4; dl++) {
        uint4 v = make_uint4(t32(a00[dl]), t32(a10[dl]), t32(a01[dl]), t32(a11[dl]));
        ((uint4*)dst)[dl] = v;
    }
}
__device__ __forceinline__ void mma_stage_fetchB(StB& st, const float* pb) {
    #pragma unroll
    for (int j = 0; j < 8; j++) st.g[j] = *(const float2*)(pb + j * 256);
}
__device__ __forceinline__ void mma_stage_storeB(unsigned* dst, const StB& st) {
    uint4 v0 = make_uint4(t32(st.g[0].x), t32(st.g[4].x), t32(st.g[1].x), t32(st.g[5].x));
    uint4 v1 = make_uint4(t32(st.g[2].x), t32(st.g[6].x), t32(st.g[3].x), t32(st.g[7].x));
    uint4 v2 = make_uint4(t32(st.g[0].y), t32(st.g[4].y), t32(st.g[1].y), t32(st.g[5].y));
    uint4 v3 = make_uint4(t32(st.g[2].y), t32(st.g[6].y), t32(st.g[3].y), t32(st.g[7].y));
    ((uint4*)dst)[0] = v0; ((uint4*)dst)[1] = v1;
    ((uint4*)dst)[2] = v2; ((uint4*)dst)[3] = v3;
}

// ---------------- fused: logmap0 + zero + weight fragment-packing ------------
#define LOG_BLOCKS (NN / 8)
__global__ __launch_bounds__(256) void k_logmap0_fused(
    const float* __restrict__ x, const float* __restrict__ We1,
    const float* __restrict__ Wa1, const float* __restrict__ Wlin,
    const float* __restrict__ We2) {
    int b = blockIdx.x;
    int tid = threadIdx.x;
    if (b >= LOG_BLOCKS) {
        int pb = b - LOG_BLOCKS;
        if (pb < 32) {
            const float* W = (pb < 16) ? Wlin : We2;
            unsigned* P = (pb < 16) ? g_WlinP : g_We2P;
            int t = (pb & 15) * 256 + tid;
            int half = t & 1;
            int tt = (t >> 1) & 127;
            int kb = (t >> 8) & 7;
            int colBlk = t >> 11;
            const float* pbs = W + ((tt >> 2) & 3) * 8 * 256 + colBlk * 128 +
                               (tt >> 4) * 8 + 2 * (tt & 3) + half * 64 +
                               kb * 32 * 256;
            StB st; mma_stage_fetchB(st, pbs);
            mma_stage_storeB(P + colBlk * 32768 + kb * 4096 + half * 2048 + tt * 16, st);
        } else {
            int t = (pb - 32) * 256 + tid;
            int m = t >> 11;
            int tt = t & 2047;
            int tid128 = tt & 127;
            int kb = (tt >> 7) & 7;
            int colBlk = tt >> 10;
            const float* W = (m == 0) ? We1 : Wa1 + (m - 1) * 256 * 256;
            unsigned* P = g_WqpP + m * 32768 + colBlk * 16384 + kb * 2048;
            int kp2 = tid128 & 15;
            int nblk = tid128 >> 4;
            int bs = kp2 >> 3;
            int kk = kp2 & 7;
            int bl4 = kk & 3;
            int breg = kk >> 2;
            int k0 = kb * 32 + kp2 * 2;
            #pragma unroll
            for (int wi = 0; wi < 8; wi++) {
                int n0 = nblk * 16 + wi * 2;
                int cabs = colBlk * 128 + n0;
                __half2 f0 = __floats2half2_rn(W[(size_t)k0 * 256 + cabs],
                                               W[(size_t)(k0 + 1) * 256 + cabs]);
                __half2 f1 = __floats2half2_rn(W[(size_t)k0 * 256 + cabs + 1],
                                               W[(size_t)(k0 + 1) * 256 + cabs + 1]);
                int gn = n0 >> 3;
                int l0 = n0 & 7;
                P[((gn * 2 + bs) * 32 + l0 * 4 + bl4) * 2 + breg] = *(unsigned*)&f0;
                P[((gn * 2 + bs) * 32 + (l0 + 1) * 4 + bl4) * 2 + breg] = *(unsigned*)&f1;
            }
        }
        return;
    }
    int node = b * 8 + (tid >> 5);
    int lane = tid & 31;
    int base = lane * 8;

    float xv[8];
    const float* xp = x + (size_t)node * D + base;
    *(float4*)&xv[0] = *(const float4*)(xp);
    *(float4*)&xv[4] = *(const float4*)(xp + 4);

    float x0 = fmaxf(__shfl_sync(0xffffffffu, xv[0], 0), 1.f + EPSF);
    float sc = acoshf(x0) / sqrtf(x0 * x0 - 1.f);

    float uo[8];
    #pragma unroll
    for (int i = 0; i < 8; i++) uo[i] = sc * xv[i];
    if (lane == 0) uo[0] = 0.f;

    float* up = g_u + (size_t)node * D + base;
    *(float4*)(up)     = *(float4*)&uo[0];
    *(float4*)(up + 4) = *(float4*)&uo[4];

    const float4 z4 = make_float4(0.f, 0.f, 0.f, 0.f);
    float* Hp = g_H + (size_t)node * D + base;
    *(float4*)(Hp)     = z4;
    *(float4*)(Hp + 4) = z4;
    if (lane == 0) g_S[node] = 0.f;
}

// ---------------- tf32 MMA GEMM with pre-packed B (128 thr, R15 shape) -------
__device__ __forceinline__ void mma_gemm_body_f32(const float* __restrict__ A,
                                                  const unsigned* __restrict__ PB,
                                                  float* __restrict__ C, int M) {
    __shared__ __align__(16) unsigned smA[2][2048];
    __shared__ __align__(16) unsigned smB[2][4096];
    int tid = threadIdx.x;
    int lane = tid & 31;
    int w = tid >> 5;
    int wm = w & 1, wn = w >> 1;
    int rowBase = blockIdx.y * 64;

    int aRow0 = rowBase + (tid >> 5) * 16 + (tid & 7);
    const float* pa0 = A + (size_t)aRow0 * 256 + ((tid >> 3) & 3) * 8;
    const float* pa1 = pa0 + 8 * 256;
    bool ok0 = aRow0 < M, ok1 = (aRow0 + 8) < M;
    const uint4* pbp = (const uint4*)(PB + blockIdx.x * 32768);

    StA stA;
    uint4 rb[8];
    mma_stage_fetchA(stA, pa0, pa1, ok0, ok1);
    #pragma unroll
    for (int q = 0; q < 8; q++) rb[q] = pbp[q * 128 + tid];
    mma_stage_storeA(&smA[0][tid * 16], stA);
    #pragma unroll
    for (int q = 0; q < 8; q++) ((uint4*)smB[0])[q * 128 + tid] = rb[q];
    __syncthreads();

    float d[2][8][4];
    #pragma unroll
    for (int t = 0; t < 2; t++)
        #pragma unroll
        for (int u = 0; u < 8; u++)
            #pragma unroll
            for (int c = 0; c < 4; c++) d[t][u][c] = 0.f;

    int buf = 0;
    for (int kb = 0; kb < 8; kb++) {
        if (kb < 7) {
            mma_stage_fetchA(stA, pa0 + (kb + 1) * 32, pa1 + (kb + 1) * 32, ok0, ok1);
            #pragma unroll
            for (int q = 0; q < 8; q++)
                rb[q] = pbp[(kb + 1) * 1024 + q * 128 + tid];
        }
        #pragma unroll
        for (int s = 0; s < 4; s++) {
            uint4 fa0 = *(const uint4*)&smA[buf][((2 * wm + 0) * 4 + s) * 128 + lane * 4];
            uint4 fa1 = *(const uint4*)&smA[buf][((2 * wm + 1) * 4 + s) * 128 + lane * 4];
            uint2 fb[8];
            #pragma unroll
            for (int u = 0; u < 8; u++)
                fb[u] = *(const uint2*)&smB[buf][wn * 2048 + (u * 4 + s) * 64 + lane * 2];
            #pragma unroll
            for (int u = 0; u < 8; u++) {
                mma_tf32(d[0][u], fa0, fb[u]);
                mma_tf32(d[1][u], fa1, fb[u]);
            }
        }
        if (kb < 7) {
            int nb = buf ^ 1;
            mma_stage_storeA(&smA[nb][tid * 16], stA);
            #pragma unroll
            for (int q = 0; q < 8; q++) ((uint4*)smB[nb])[q * 128 + tid] = rb[q];
            __syncthreads();
            buf = nb;
        }
    }

    int colBase = blockIdx.x * 128;
    #pragma unroll
    for (int t = 0; t < 2; t++) {
        int r0 = rowBase + (2 * wm + t) * 16 + (lane >> 2);
        int r1 = r0 + 8;
        #pragma unroll
        for (int u = 0; u < 8; u++) {
            int c0 = colBase + wn * 64 + u * 8 + (lane & 3) * 2;
            if (r0 < M)
                *(float2*)(C + (size_t)r0 * 256 + c0) =
                    make_float2(d[t][u][0], d[t][u][1]);
            if (r1 < M)
                *(float2*)(C + (size_t)r1 * 256 + c0) =
                    make_float2(d[t][u][2], d[t][u][3]);
        }
    }
}

__global__ __launch_bounds__(128, 3) void mma_lin() {
    mma_gemm_body_f32(g_u, g_WlinP, g_h, NN);
}
__global__ __launch_bounds__(128, 3) void mma_agg() {
    mma_gemm_body_f32(g_H, g_We2P, g_agg, NN);
}

// ---------------- fp16 MMA GEMM (m16n8k16) with pre-packed B (128 thr) -------
__global__ __launch_bounds__(128, 3) void mma_qph() {
    int z = blockIdx.z;
    const __half* A = (z == 0) ? g_xph : g_xtanh;
    __half* C = (z == 0) ? g_Qh : (z == 1 ? g_P1h : g_P2h);
    const int M = NN;

    __shared__ __align__(16) unsigned smA[2][1024];
    __shared__ __align__(16) unsigned smB[2][2048];
    int tid = threadIdx.x;
    int lane = tid & 31;
    int w = tid >> 5;
    int wm = w & 1, wn = w >> 1;
    int rowBase = blockIdx.y * 64;
    int colBase = blockIdx.x * 128;

    int ar = tid >> 1;
    int as = tid & 1;
    int aRow = rowBase + ar;
    bool aok = aRow < M;
    const __half* pa = A + (size_t)aRow * 256 + as * 16;
    int ag = ar >> 4;
    int rr = ar & 15;
    int abase = ((ag * 2 + as) * 32 + (rr & 7) * 4) * 4 + (rr >> 3);
    const uint4* pbp = (const uint4*)(g_WqpP + z * 32768 + blockIdx.x * 16384);

    const uint4 zz = make_uint4(0u, 0u, 0u, 0u);
    uint4 va, vb, rb[4];

    va = aok ? *(const uint4*)(pa)     : zz;
    vb = aok ? *(const uint4*)(pa + 8) : zz;
    #pragma unroll
    for (int q = 0; q < 4; q++) rb[q] = pbp[q * 128 + tid];

    {
        unsigned* dA = &smA[0][abase];
        dA[0] = va.x; dA[4] = va.y; dA[8]  = va.z; dA[12] = va.w;
        dA[2] = vb.x; dA[6] = vb.y; dA[10] = vb.z; dA[14] = vb.w;
        #pragma unroll
        for (int q = 0; q < 4; q++) ((uint4*)smB[0])[q * 128 + tid] = rb[q];
    }
    __syncthreads();

    float d[2][8][4];
    #pragma unroll
    for (int t = 0; t < 2; t++)
        #pragma unroll
        for (int u = 0; u < 8; u++)
            #pragma unroll
            for (int c = 0; c < 4; c++) d[t][u][c] = 0.f;

    int buf = 0;
    for (int kb = 0; kb < 8; kb++) {
        if (kb < 7) {
            const __half* pan = pa + (kb + 1) * 32;
            va = aok ? *(const uint4*)(pan)     : zz;
            vb = aok ? *(const uint4*)(pan + 8) : zz;
            #pragma unroll
            for (int q = 0; q < 4; q++)
                rb[q] = pbp[(kb + 1) * 512 + q * 128 + tid];
        }
        #pragma unroll
        for (int s = 0; s < 2; s++) {
            uint4 fa0 = *(const uint4*)&smA[buf][(((wm * 2 + 0) * 2 + s) * 32 + lane) * 4];
            uint4 fa1 = *(const uint4*)&smA[buf][(((wm * 2 + 1) * 2 + s) * 32 + lane) * 4];
            uint2 fb[8];
            #pragma unroll
            for (int u = 0; u < 8; u++)
                fb[u] = *(const uint2*)&smB[buf][(((wn * 8 + u) * 2 + s) * 32 + lane) * 2];
            #pragma unroll
            for (int u = 0; u < 8; u++) {
                mma_f16(d[0][u], fa0, fb[u]);
                mma_f16(d[1][u], fa1, fb[u]);
            }
        }
        if (kb < 7) {
            int nb = buf ^ 1;
            unsigned* dA = &smA[nb][abase];
            dA[0] = va.x; dA[4] = va.y; dA[8]  = va.z; dA[12] = va.w;
            dA[2] = vb.x; dA[6] = vb.y; dA[10] = vb.z; dA[14] = vb.w;
            #pragma unroll
            for (int q = 0; q < 4; q++) ((uint4*)smB[nb])[q * 128 + tid] = rb[q];
            __syncthreads();
            buf = nb;
        }
    }

    #pragma unroll
    for (int t = 0; t < 2; t++) {
        int r0 = rowBase + (2 * wm + t) * 16 + (lane >> 2);
        int r1 = r0 + 8;
        #pragma unroll
        for (int u = 0; u < 8; u++) {
            int c0 = colBase + wn * 64 + u * 8 + (lane & 3) * 2;
            if (r0 < M)
                *(__half2*)(C + (size_t)r0 * 256 + c0) =
                    __floats2half2_rn(d[t][u][0], d[t][u][1]);
            if (r1 < M)
                *(__half2*)(C + (size_t)r1 * 256 + c0) =
                    __floats2half2_rn(d[t][u][2], d[t][u][3]);
        }
    }
}

// ---------------- node prep: one warp per node --------------------------------
__global__ __launch_bounds__(256) void k_node_xp(const float* __restrict__ bias) {
    int node = blockIdx.x * 8 + (threadIdx.x >> 5);
    int lane = threadIdx.x & 31;
    int base = lane * 8;

    float h[8];
    const float* hp = g_h + (size_t)node * D + base;
    *(float4*)&h[0] = *(const float4*)(hp);
    *(float4*)&h[4] = *(const float4*)(hp + 4);
    if (lane == 0) h[0] = 0.f;

    float acc = 0.f;
    #pragma unroll
    for (int i = 0; i < 8; i++) acc += h[i] * h[i];
    float r1 = warpSum(acc);
    float nn = sqrtf(fmaxf(r1, EPSF));
    float sh_n = sinhf(nn) / nn;
    float xp00 = coshf(nn);
    float xp0[8];
    #pragma unroll
    for (int i = 0; i < 8; i++) xp0[i] = sh_n * h[i];
    if (lane == 0) xp0[0] = xp00;

    float b[8];
    *(float4*)&b[0] = *(const float4*)(bias + base);
    *(float4*)&b[4] = *(const float4*)(bias + base + 4);
    if (lane == 0) b[0] = 0.f;

    acc = 0.f;
    #pragma unroll
    for (int i = 0; i < 8; i++) acc += xp0[i] * b[i];
    float c = warpSum(acc);
    float fac = c / (1.f + xp00);
    float u[8];
    #pragma unroll
    for (int i = 0; i < 8; i++) u[i] = b[i] + fac * xp0[i];
    if (lane == 0) u[0] += fac;

    acc = 0.f;
    #pragma unroll
    for (int i = 0; i < 8; i++) acc += u[i] * u[i];
    float su2 = warpSum(acc);
    float lin = su2 - 2.f * c * c;
    float nu = sqrtf(fmaxf(lin, EPSF));
    float ch = coshf(nu), sh = sinhf(nu) / nu;

    float xp[8];
    #pragma unroll
    for (int i = 0; i < 8; i++) xp[i] = ch * xp0[i] + sh * u[i];
    float* xpp = g_xp + (size_t)node * D + base;
    *(float4*)(xpp)     = *(float4*)&xp[0];
    *(float4*)(xpp + 4) = *(float4*)&xp[4];

    {
        __half2 q0 = __floats2half2_rn(xp[0], xp[1]);
        __half2 q1 = __floats2half2_rn(xp[2], xp[3]);
        __half2 q2 = __floats2half2_rn(xp[4], xp[5]);
        __half2 q3 = __floats2half2_rn(xp[6], xp[7]);
        uint4 o;
        o.x = *(unsigned*)&q0; o.y = *(unsigned*)&q1;
        o.z = *(unsigned*)&q2; o.w = *(unsigned*)&q3;
        *(uint4*)(g_xph + (size_t)node * D + base) = o;
    }

    float xpc0 = ch * xp00 + sh * c;
    float x0c = fmaxf(xpc0, 1.f + EPSF);
    float sc = acoshf(x0c) / sqrtf(x0c * x0c - 1.f);
    float xt[8];
    #pragma unroll
    for (int i = 0; i < 8; i++) xt[i] = sc * xp[i];
    if (lane == 0) xt[0] = 0.f;
    {
        __half2 q0 = __floats2half2_rn(xt[0], xt[1]);
        __half2 q1 = __floats2half2_rn(xt[2], xt[3]);
        __half2 q2 = __floats2half2_rn(xt[4], xt[5]);
        __half2 q3 = __floats2half2_rn(xt[6], xt[7]);
        uint4 o;
        o.x = *(unsigned*)&q0; o.y = *(unsigned*)&q1;
        o.z = *(unsigned*)&q2; o.w = *(unsigned*)&q3;
        *(uint4*)(g_xtanh + (size_t)node * D + base) = o;
    }
}

// ---------------- edge kernel: 64 edges per block (8 per warp) ---------------
__global__ __launch_bounds__(256) void k_edge(
    const float* __restrict__ eattr, const int* __restrict__ row,
    const int* __restrict__ col, const float* __restrict__ emask,
    const float* __restrict__ Wa1, const float* __restrict__ ba1,
    const float* __restrict__ Wa2, const float* __restrict__ ba2,
    const float* __restrict__ We1, const float* __restrict__ be1) {
    __shared__ float sw[8][256];
    int tid = threadIdx.x;
    sw[0][tid] = Wa1[512 * D + tid];
    sw[1][tid] = Wa1[513 * D + tid];
    sw[2][tid] = ba1[tid];
    sw[3][tid] = Wa2[tid];
    sw[4][tid] = We1[tid];
    sw[5][tid] = We1[256 * D + tid];
    sw[6][tid] = We1[257 * D + tid];
    sw[7][tid] = be1[tid];
    __syncthreads();

    int warp = tid >> 5;
    int lane = tid & 31;
    int base = lane * 8;
    float ba2v = ba2[0];

    // prefetch all 8 edge indices up-front (MLP for the index chain)
    int er[8], ec[8];
    #pragma unroll
    for (int it = 0; it < 8; it++) {
        int e = blockIdx.x * 64 + it * 8 + warp;
        er[it] = row[e];
        ec[it] = col[e];
    }

    #pragma unroll
    for (int it = 0; it < 8; it++) {
        int e = blockIdx.x * 64 + it * 8 + warp;
        int r = er[it];
        int c = ec[it];

        float xr[8], xc[8];
        ld8h(g_xph + (size_t)r * D + base, xr);
        ld8h(g_xph + (size_t)c * D + base, xc);

        float part = 0.f;
        #pragma unroll
        for (int i = 0; i < 8; i++) part -= xr[i] * xc[i];
        part = warpSum(part);

        float x0 = __shfl_sync(0xffffffffu, xr[0], 0);
        float y0 = __shfl_sync(0xffffffffu, xc[0], 0);

        float a = fmaxf(part + 2.f * x0 * y0, 1.f + EPSF);
        float dd = acoshf(a);
        float q = sqrtf(a * a - 1.f);
        float s = dd / q;
        float v0 = s * (y0 - a * x0);
        float beta = -v0 / (1.f + x0);
        float alpha = beta - s * a;

        float ea0 = eattr[e];
        float m = emask[e];

        float P1v[8], P2v[8];
        ld8h(g_P1h + (size_t)r * D + base, P1v);
        ld8h(g_P2h + (size_t)c * D + base, P2v);

        float lp = 0.f;
        #pragma unroll
        for (int i = 0; i < 8; i++) {
            int j = base + i;
            float ha = P1v[i] + P2v[i] + ea0 * sw[0][j] + dd * sw[1][j] + sw[2][j];
            lp += silu_fast(ha) * sw[3][j];
        }
        lp = warpSum(lp);
        float att = m * sigm_fast(lp + ba2v);

        float QR[8], QC[8];
        ld8h(g_Qh + (size_t)r * D + base, QR);
        ld8h(g_Qh + (size_t)c * D + base, QC);

        float val[8];
        #pragma unroll
        for (int i = 0; i < 8; i++) {
            int j = base + i;
            float hm = alpha * QR[i] + s * QC[i] + beta * sw[4][j] +
                       ea0 * sw[5][j] + dd * sw[6][j] + sw[7][j];
            val[i] = att * silu_fast(hm);
        }

        float* Hr = g_H + (size_t)r * D + base;
        asm volatile("red.global.add.v4.f32 [%0], {%1,%2,%3,%4};"
                     :: "l"(Hr), "f"(val[0]), "f"(val[1]), "f"(val[2]), "f"(val[3])
                     : "memory");
        asm volatile("red.global.add.v4.f32 [%0], {%1,%2,%3,%4};"
                     :: "l"(Hr + 4), "f"(val[4]), "f"(val[5]), "f"(val[6]), "f"(val[7])
                     : "memory");
        if (lane == 0) atomicAdd(&g_S[r], att);
    }
}

// ---------------- final node kernel: one warp per node -----------------------
__global__ __launch_bounds__(256) void k_final(const float* __restrict__ be2,
                                               const float* __restrict__ lng,
                                               const float* __restrict__ lnb,
                                               float* __restrict__ out) {
    int node = blockIdx.x * 8 + (threadIdx.x >> 5);
    int lane = threadIdx.x & 31;
    int base = lane * 8;

    float Sv = g_S[node];
    float ag[8], be[8], xp[8];
    const float* agp = g_agg + (size_t)node * D + base;
    *(float4*)&ag[0] = *(const float4*)(agp);
    *(float4*)&ag[4] = *(const float4*)(agp + 4);
    *(float4*)&be[0] = *(const float4*)(be2 + base);
    *(float4*)&be[4] = *(const float4*)(be2 + base + 4);
    const float* xpp = g_xp + (size_t)node * D + base;
    *(float4*)&xp[0] = *(const float4*)(xpp);
    *(float4*)&xp[4] = *(const float4*)(xpp + 4);

    #pragma unroll
    for (int i = 0; i < 8; i++) ag[i] += Sv * be[i];
    if (lane == 0) ag[0] = 0.f;

    float xp0 = __shfl_sync(0xffffffffu, xp[0], 0);

    float acc = 0.f;
    #pragma unroll
    for (int i = 0; i < 8; i++) acc += xp[i] * ag[i];
    float cc = warpSum(acc);
    float fac = cc / (1.f + xp0);
    float sup[8];
    #pragma unroll
    for (int i = 0; i < 8; i++) sup[i] = ag[i] + fac * xp[i];
    if (lane == 0) sup[0] += fac;

    acc = 0.f;
    #pragma unroll
    for (int i = 0; i < 8; i++) acc += sup[i] * sup[i];
    float su2 = warpSum(acc);
    float lin = su2 - 2.f * cc * cc;
    float nu = sqrtf(fmaxf(lin, EPSF));
    float ch = coshf(nu), sh = sinhf(nu) / nu;

    float y[8];
    #pragma unroll
    for (int i = 0; i < 8; i++) y[i] = ch * xp[i] + sh * sup[i];
    float y0 = ch * xp0 + sh * cc;

    float y0c = fmaxf(y0, 1.f + EPSF);
    float sc = acoshf(y0c) / sqrtf(y0c * y0c - 1.f);
    float xo[8];
    #pragma unroll
    for (int i = 0; i < 8; i++) xo[i] = sc * y[i];
    if (lane == 0) xo[0] = 0.f;

    acc = 0.f;
    #pragma unroll
    for (int i = 0; i < 8; i++) acc += xo[i];
    float mean = warpSum(acc) * (1.f / 255.f);
    float dev[8];
    #pragma unroll
    for (int i = 0; i < 8; i++) dev[i] = xo[i] - mean;
    if (lane == 0) dev[0] = 0.f;
    acc = 0.f;
    #pragma unroll
    for (int i = 0; i < 8; i++) acc += dev[i] * dev[i];
    float var = warpSum(acc) * (1.f / 255.f);
    float inv = 1.f / sqrtf(var + 1e-5f);

    float sl[8];
    #pragma unroll
    for (int i = 0; i < 8; i++) {
        int j = base + i;
        float lg = (j > 0) ? lng[j - 1] : 0.f;
        float lb = (j > 0) ? lnb[j - 1] : 0.f;
        float ln = dev[i] * inv * lg + lb;
        sl[i] = siluf(ln);
    }
    if (lane == 0) sl[0] = 0.f;

    acc = 0.f;
    #pragma unroll
    for (int i = 0; i < 8; i++) acc += sl[i] * sl[i];
    float n2 = warpSum(acc);
    float nn = sqrtf(fmaxf(n2, EPSF));
    float shn = sinhf(nn) / nn;

    float o[8];
    #pragma unroll
    for (int i = 0; i < 8; i++) o[i] = shn * sl[i];
    if (lane == 0) o[0] = coshf(nn);
    float* op = out + (size_t)node * D + base;
    *(float4*)(op)     = *(float4*)&o[0];
    *(float4*)(op + 4) = *(float4*)&o[4];
}

// ---------------- launch -----------------------------------------------------
extern "C" void kernel_launch(void* const* d_in, const int* in_sizes, int n_in,
                              void* d_out, int out_size) {
    const float* x     = (const float*)d_in[0];
    const float* eattr = (const float*)d_in[1];
    const int*   row   = (const int*)d_in[2];
    const int*   col   = (const int*)d_in[3];
    const float* emask = (const float*)d_in[5];
    const float* W_lin = (const float*)d_in[6];
    const float* bias  = (const float*)d_in[7];
    const float* W_e1  = (const float*)d_in[8];
    const float* b_e1  = (const float*)d_in[9];
    const float* W_e2  = (const float*)d_in[10];
    const float* b_e2  = (const float*)d_in[11];
    const float* W_a1  = (const float*)d_in[12];
    const float* b_a1  = (const float*)d_in[13];
    const float* W_a2  = (const float*)d_in[14];
    const float* b_a2  = (const float*)d_in[15];
    const float* ln_g  = (const float*)d_in[16];
    const float* ln_b  = (const float*)d_in[17];
    float* out = (float*)d_out;

    dim3 gMma(2, (NN + 63) / 64);
    dim3 gMmaQP(2, (NN + 63) / 64, 3);

    k_logmap0_fused<<<LOG_BLOCKS + 56, 256>>>(x, W_e1, W_a1, W_lin, W_e2);
    mma_lin<<<gMma, 128>>>();                           // tf32, packed B
    k_node_xp<<<NN / 8, 256>>>(bias);
    mma_qph<<<gMmaQP, 128>>>();                         // fp16, packed B
    k_edge<<<NE / 64, 256>>>(eattr, row, col, emask, W_a1, b_a1, W_a2, b_a2, W_e1, b_e1);
    mma_agg<<<gMma, 128>>>();                           // tf32, packed B
    k_final<<<NN / 8, 256>>>(b_e2, ln_g, ln_b, out);
}